// round 14
// baseline (speedup 1.0000x reference)
#include <cuda_runtime.h>
#include <cuda_fp16.h>

typedef unsigned int u32;

#define B_   8
#define N_   1024
#define C_   1024
#define H_   16
#define D_   64
#define M_   (B_ * N_)     // 8192
#define QKVC 3072
#define BH_  (B_ * H_)     // 128

// ---------------- allocation-free scratch (device globals, fp16) ----------
__device__ __align__(256) __half g_xh[(size_t)M_ * C_];
__device__ __align__(256) __half g_wqh[(size_t)QKVC * C_];
__device__ __align__(256) __half g_wph[(size_t)C_ * C_];
__device__ __align__(256) __half g_qh[(size_t)BH_ * N_ * D_];
__device__ __align__(256) __half g_kh[(size_t)BH_ * N_ * D_];
__device__ __align__(256) __half g_vTh[(size_t)BH_ * D_ * N_];
__device__ __align__(256) __half g_ch[(size_t)M_ * C_];

// ---------------- helpers ----------------
__device__ __forceinline__ u32 smem_u32(const void* p) {
    u32 a;
    asm("{ .reg .u64 t; cvta.to.shared.u64 t, %1; cvt.u32.u64 %0, t; }" : "=r"(a) : "l"(p));
    return a;
}
#define CP16(dst, src) \
    asm volatile("cp.async.cg.shared.global [%0], [%1], 16;" :: "r"(dst), "l"(src) : "memory")
#define CP_COMMIT() asm volatile("cp.async.commit_group;" ::: "memory")
#define CP_WAIT(n)  asm volatile("cp.async.wait_group %0;" :: "n"(n) : "memory")

__device__ __forceinline__ void ldm4(u32& r0, u32& r1, u32& r2, u32& r3, u32 a) {
    asm volatile("ldmatrix.sync.aligned.m8n8.x4.shared.b16 {%0,%1,%2,%3}, [%4];"
        : "=r"(r0), "=r"(r1), "=r"(r2), "=r"(r3) : "r"(a));
}
__device__ __forceinline__ void mma16816(float* c, const u32* a, const u32* b) {
    asm volatile(
        "mma.sync.aligned.m16n8k16.row.col.f32.f16.f16.f32 "
        "{%0,%1,%2,%3}, {%4,%5,%6,%7}, {%8,%9}, {%0,%1,%2,%3};"
        : "+f"(c[0]), "+f"(c[1]), "+f"(c[2]), "+f"(c[3])
        : "r"(a[0]), "r"(a[1]), "r"(a[2]), "r"(a[3]), "r"(b[0]), "r"(b[1]));
}

// ---------------------------------------------------------------------------
// QKV GEMM: 1-term fp16. 256 thr, 2 CTAs/SM, MA4 NA4, 3-stage ring. (r13)
// ---------------------------------------------------------------------------
#define QK_PART  10240
#define QK_STAGE (2 * QK_PART)
#define QK_SMEM  (3 * QK_STAGE)   // 61440

__global__ void __launch_bounds__(256, 2) qkv_gemm()
{
    constexpr int NC = 32;
    constexpr int MA = 4;
    constexpr int NA = 4;

    extern __shared__ char smem[];
    const u32 sb   = smem_u32(smem);
    const int tid  = threadIdx.x;
    const int wid  = tid >> 5, lane = tid & 31;
    const int g    = lane >> 2, t = lane & 3;
    const int bn   = blockIdx.x * 128;
    const int bm   = blockIdx.y * 128;
    const int wm   = (wid & 1) * 64;
    const int wn   = (wid >> 1) * 32;

    const __half *Ah = g_xh + (size_t)bm * C_;
    const __half *Bh = g_wqh + (size_t)bn * C_;

    float acc[MA][NA][4];
    #pragma unroll
    for (int i = 0; i < MA; i++)
        #pragma unroll
        for (int j = 0; j < NA; j++)
            #pragma unroll
            for (int r = 0; r < 4; r++) acc[i][j][r] = 0.0f;

    auto issue_loads = [&](int ck, int s) {
        const int kofs = ck * 32;
        const u32 base = sb + s * QK_STAGE;
        #pragma unroll
        for (int i = tid; i < 128 * 4; i += 256) {
            int r = i >> 2, sgm = i & 3;
            u32 off = (u32)(r * 80 + sgm * 16);
            const size_t go = (size_t)r * C_ + kofs + sgm * 8;
            CP16(base + off,           Ah + go);
            CP16(base + QK_PART + off, Bh + go);
        }
        CP_COMMIT();
    };

    const u32 arow = (u32)((wm + (lane & 15)) * 80 + ((lane >> 4) << 4));
    const u32 brow = (u32)((wn + (lane & 7) + ((lane >> 4) << 3)) * 80 + (((lane >> 3) & 1) << 4));

    auto do_compute = [&](int s) {
        const u32 abase = sb + s * QK_STAGE;
        const u32 bbase = abase + QK_PART;
        #pragma unroll
        for (int ks = 0; ks < 2; ks++) {
            const u32 kb = ks * 32;
            u32 a_hi[MA][4], b_hi[NA][2];
            #pragma unroll
            for (int ma = 0; ma < MA; ma++) {
                u32 ad = abase + arow + ma * 16 * 80 + kb;
                ldm4(a_hi[ma][0], a_hi[ma][1], a_hi[ma][2], a_hi[ma][3], ad);
            }
            #pragma unroll
            for (int p = 0; p < NA / 2; p++) {
                u32 bd = bbase + brow + p * 16 * 80 + kb;
                ldm4(b_hi[2*p][0], b_hi[2*p][1], b_hi[2*p+1][0], b_hi[2*p+1][1], bd);
            }
            #pragma unroll
            for (int ma = 0; ma < MA; ma++)
                #pragma unroll
                for (int na = 0; na < NA; na++)
                    mma16816(acc[ma][na], a_hi[ma], b_hi[na]);
        }
    };

    issue_loads(0, 0);
    issue_loads(1, 1);
    for (int ck = 0; ck < NC; ck++) {
        const int s = ck % 3;
        if (ck + 2 < NC) { issue_loads(ck + 2, (ck + 2) % 3); CP_WAIT(2); }
        else if (ck + 1 < NC) { CP_WAIT(1); }
        else { CP_WAIT(0); }
        __syncthreads();
        do_compute(s);
        __syncthreads();
    }

    #pragma unroll
    for (int ma = 0; ma < MA; ma++)
        #pragma unroll
        for (int na = 0; na < NA; na++)
            #pragma unroll
            for (int half = 0; half < 2; half++) {
                const int row = bm + wm + ma * 16 + g + half * 8;
                const int col = bn + wn + na * 8 + t * 2;
                float v0 = acc[ma][na][half * 2 + 0];
                float v1 = acc[ma][na][half * 2 + 1];

                const int which = col >> 10;
                const int c     = col & 1023;
                const int h     = c >> 6;
                const int d0    = c & 63;
                const int b8    = row >> 10;
                const int n     = row & 1023;
                const int bh    = b8 * H_ + h;
                if (which == 0) {
                    const size_t base = ((size_t)bh * N_ + n) * D_ + d0;
                    *(__half2*)(g_qh + base) =
                        __halves2half2(__float2half(v0 * 0.125f), __float2half(v1 * 0.125f));
                } else if (which == 1) {
                    const size_t base = ((size_t)bh * N_ + n) * D_ + d0;
                    *(__half2*)(g_kh + base) =
                        __halves2half2(__float2half(v0), __float2half(v1));
                } else {
                    const size_t vb = (size_t)bh * D_ * N_ + n;
                    g_vTh[vb + (size_t)d0 * N_]       = __float2half(v0);
                    g_vTh[vb + (size_t)(d0 + 1) * N_] = __float2half(v1);
                }
            }
}

// ---------------------------------------------------------------------------
// Fused flash-style attention: per block = (bh, 16-row q slab). 2 CTAs/SM.
// Phase A: S = qh@khT (1-term). Phase B: softmax -> attn fp32 + P fp16 in smem.
// Phase C: ctx = P@Vh (V ring reuses K ring space) -> g_ch.
// Smem: Q 2304 | K/V ring 2x18432 | S 16x4144 = 105472 total.
// ---------------------------------------------------------------------------
#define FQ_OFF  0
#define FK_OFF  2304
#define FKSTG   18432
#define FS_OFF  (FK_OFF + 2 * FKSTG)     // 39168
#define FS_PIT  4144
#define FA_SMEM (FS_OFF + 16 * FS_PIT)   // 105472

__global__ void __launch_bounds__(256, 2) fa_kernel(float* __restrict__ attn)
{
    extern __shared__ char smem[];
    const u32 sb   = smem_u32(smem);
    const int tid  = threadIdx.x;
    const int wid  = tid >> 5, lane = tid & 31;
    const int g    = lane >> 2, t = lane & 3;

    const int bh   = blockIdx.x >> 6;
    const int row0 = (blockIdx.x & 63) * 16;
    const int b8   = bh >> 4, h = bh & 15;

    const __half* Qh = g_qh + ((size_t)bh * N_ + row0) * D_;
    const __half* Kh = g_kh + (size_t)bh * N_ * D_;
    const __half* Vh = g_vTh + (size_t)bh * D_ * N_;

    // Q slab: 16 rows x 128B, pitch 144 (128 float4s; tid<128)
    if (tid < 128) {
        int r = tid >> 3, sgm = tid & 7;
        *(float4*)(smem + FQ_OFF + (u32)(r * 144 + sgm * 16)) =
            *(const float4*)(Qh + r * D_ + sgm * 8);
    }

    auto issueK = [&](int c, int s) {
        const u32 base = sb + FK_OFF + s * FKSTG;
        const size_t ko = (size_t)c * 128 * D_;
        #pragma unroll
        for (int i = tid; i < 128 * 8; i += 256) {
            int r = i >> 3, sgm = i & 7;
            CP16(base + (u32)(r * 144 + sgm * 16), Kh + ko + r * D_ + sgm * 8);
        }
        CP_COMMIT();
    };

    // ================= Phase A: scores (warp = 16 rows x 16 cols) ==========
    {
        const int wn = wid * 16;
        const u32 arow = (u32)((lane & 15) * 144 + ((lane >> 4) << 4));
        const u32 brow = (u32)((wn + (lane & 7) + ((lane >> 4) << 3)) * 144 + (((lane >> 3) & 1) << 4));

        issueK(0, 0);
        issueK(1, 1);
        for (int c = 0; c < 8; c++) {
            if (c < 7) CP_WAIT(1); else CP_WAIT(0);
            __syncthreads();

            const u32 kb0 = sb + FK_OFF + (c & 1) * FKSTG;
            float acc[2][4];
            #pragma unroll
            for (int j = 0; j < 2; j++)
                #pragma unroll
                for (int r = 0; r < 4; r++) acc[j][r] = 0.0f;

            #pragma unroll
            for (int ks = 0; ks < 4; ks++) {
                const u32 kb = ks * 32;
                u32 a_hi[4], b_hi[2][2];
                ldm4(a_hi[0], a_hi[1], a_hi[2], a_hi[3], sb + FQ_OFF + arow + kb);
                ldm4(b_hi[0][0], b_hi[0][1], b_hi[1][0], b_hi[1][1], kb0 + brow + kb);
                mma16816(acc[0], a_hi, b_hi[0]);
                mma16816(acc[1], a_hi, b_hi[1]);
            }

            #pragma unroll
            for (int na = 0; na < 2; na++)
                #pragma unroll
                for (int half = 0; half < 2; half++) {
                    int row = g + half * 8;
                    int col = c * 128 + wn + na * 8 + t * 2;
                    *(float2*)(smem + FS_OFF + row * FS_PIT + col * 4) =
                        make_float2(acc[na][half * 2], acc[na][half * 2 + 1]);
                }

            __syncthreads();
            if (c + 2 < 8) issueK(c + 2, c & 1);
        }
    }

    // ====== Phase B: softmax (2 rows/warp); attn fp32 out; P fp16 in place ==
    #pragma unroll
    for (int rr = 0; rr < 2; rr++) {
        const int r = wid * 2 + rr;
        char* Srow = smem + FS_OFF + r * FS_PIT;
        float4 f[8];
        float m = -1e30f;
        #pragma unroll
        for (int i = 0; i < 8; i++) {
            f[i] = *(const float4*)(Srow + (lane + i * 32) * 16);
            m = fmaxf(m, fmaxf(fmaxf(f[i].x, f[i].y), fmaxf(f[i].z, f[i].w)));
        }
        #pragma unroll
        for (int o = 16; o > 0; o >>= 1) m = fmaxf(m, __shfl_xor_sync(0xffffffffu, m, o));
        float s = 0.0f;
        #pragma unroll
        for (int i = 0; i < 8; i++) {
            f[i].x = __expf(f[i].x - m); f[i].y = __expf(f[i].y - m);
            f[i].z = __expf(f[i].z - m); f[i].w = __expf(f[i].w - m);
            s += f[i].x + f[i].y + f[i].z + f[i].w;
        }
        #pragma unroll
        for (int o = 16; o > 0; o >>= 1) s += __shfl_xor_sync(0xffffffffu, s, o);
        const float inv = 1.0f / s;

        float* ap = attn + ((size_t)bh * N_ + row0 + r) * N_;
        #pragma unroll
        for (int i = 0; i < 8; i++) {
            float4 p = make_float4(f[i].x * inv, f[i].y * inv, f[i].z * inv, f[i].w * inv);
            *(float4*)(ap + (lane + i * 32) * 4) = p;
            const int cb = (lane + i * 32) * 8;     // 4 fp16 = 8 bytes
            *(__half2*)(Srow + cb)     = __halves2half2(__float2half(p.x), __float2half(p.y));
            *(__half2*)(Srow + cb + 4) = __halves2half2(__float2half(p.z), __float2half(p.w));
        }
    }
    __syncthreads();

    // ================= Phase C: ctx = P @ V (V ring reuses K ring) ==========
    {
        auto issueV = [&](int c, int s) {
            const u32 base = sb + FK_OFF + s * FKSTG;
            const int ko = c * 128;
            #pragma unroll
            for (int i = tid; i < 64 * 16; i += 256) {
                int r = i >> 4, sgm = i & 15;
                CP16(base + (u32)(r * 272 + sgm * 16), Vh + (size_t)r * N_ + ko + sgm * 8);
            }
            CP_COMMIT();
        };

        const int wn8 = wid * 8;
        const u32 arow = sb + FS_OFF + (u32)((lane & 15) * FS_PIT + ((lane >> 4) << 4));
        const u32 brow = (u32)((wn8 + (lane & 7)) * 272 + ((lane >> 3) << 4));

        float acc_e[4] = {0, 0, 0, 0}, acc_o[4] = {0, 0, 0, 0};

        issueV(0, 0);
        issueV(1, 1);
        for (int c = 0; c < 8; c++) {
            if (c < 7) CP_WAIT(1); else CP_WAIT(0);
            __syncthreads();

            const u32 vb = sb + FK_OFF + (c & 1) * FKSTG;
            #pragma unroll
            for (int kp = 0; kp < 4; kp++) {
                u32 bh4[4];
                ldm4(bh4[0], bh4[1], bh4[2], bh4[3], vb + brow + kp * 64);
                #pragma unroll
                for (int sub = 0; sub < 2; sub++) {
                    const int ks = kp * 2 + sub;
                    u32 a_hi[4];
                    ldm4(a_hi[0], a_hi[1], a_hi[2], a_hi[3], arow + c * 256 + ks * 32);
                    const u32 bf[2] = { bh4[sub * 2], bh4[sub * 2 + 1] };
                    mma16816(sub ? acc_o : acc_e, a_hi, bf);
                }
            }
            __syncthreads();
            if (c + 2 < 8) issueV(c + 2, c & 1);
        }

        #pragma unroll
        for (int r = 0; r < 4; r++) acc_e[r] += acc_o[r];

        #pragma unroll
        for (int half = 0; half < 2; half++) {
            const int lrow = g + half * 8;
            const int col  = wn8 + t * 2;
            const size_t base = ((size_t)(b8 * N_ + row0 + lrow)) * C_ + h * 64 + col;
            *(__half2*)(g_ch + base) =
                __halves2half2(__float2half(acc_e[half * 2 + 0]),
                               __float2half(acc_e[half * 2 + 1]));
        }
    }
}

// ---------------------------------------------------------------------------
// Projection GEMM: out = ch @ wph + bias (1-term). 2 CTAs/SM. (r13)
// ---------------------------------------------------------------------------
#define PJ_PART  10240
#define PJ_STAGE (2 * PJ_PART)
#define PJ_SMEM  (3 * PJ_STAGE)   // 61440

__global__ void __launch_bounds__(256, 2) proj_gemm(float* __restrict__ out,
                                                    const float* __restrict__ bias)
{
    constexpr int NC = 32;
    constexpr int MA = 4;
    constexpr int NA = 4;

    extern __shared__ char smem[];
    const u32 sb   = smem_u32(smem);
    const int tid  = threadIdx.x;
    const int wid  = tid >> 5, lane = tid & 31;
    const int g    = lane >> 2, t = lane & 3;
    const int bn   = blockIdx.x * 128;
    const int bm   = blockIdx.y * 128;
    const int wm   = (wid & 1) * 64;
    const int wn   = (wid >> 1) * 32;

    const __half *Ah = g_ch + (size_t)bm * C_;
    const __half *Bh = g_wph + (size_t)bn * C_;

    float acc[MA][NA][4];
    #pragma unroll
    for (int i = 0; i < MA; i++)
        #pragma unroll
        for (int j = 0; j < NA; j++)
            #pragma unroll
            for (int r = 0; r < 4; r++) acc[i][j][r] = 0.0f;

    auto issue_loads = [&](int ck, int s) {
        const int kofs = ck * 32;
        const u32 base = sb + s * PJ_STAGE;
        #pragma unroll
        for (int i = tid; i < 128 * 4; i += 256) {
            int r = i >> 2, sgm = i & 3;
            u32 off = (u32)(r * 80 + sgm * 16);
            const size_t go = (size_t)r * C_ + kofs + sgm * 8;
            CP16(base + off,           Ah + go);
            CP16(base + PJ_PART + off, Bh + go);
        }
        CP_COMMIT();
    };

    const u32 arow = (u32)((wm + (lane & 15)) * 80 + ((lane >> 4) << 4));
    const u32 brow = (u32)((wn + (lane & 7) + ((lane >> 4) << 3)) * 80 + (((lane >> 3) & 1) << 4));

    auto do_compute = [&](int s) {
        const u32 abase = sb + s * PJ_STAGE;
        const u32 bbase = abase + PJ_PART;
        #pragma unroll
        for (int ks = 0; ks < 2; ks++) {
            const u32 kb = ks * 32;
            u32 a_hi[MA][4], b_hi[NA][2];
            #pragma unroll
            for (int ma = 0; ma < MA; ma++) {
                u32 ad = abase + arow + ma * 16 * 80 + kb;
                ldm4(a_hi[ma][0], a_hi[ma][1], a_hi[ma][2], a_hi[ma][3], ad);
            }
            #pragma unroll
            for (int p = 0; p < NA / 2; p++) {
                u32 bd = bbase + brow + p * 16 * 80 + kb;
                ldm4(b_hi[2*p][0], b_hi[2*p][1], b_hi[2*p+1][0], b_hi[2*p+1][1], bd);
            }
            #pragma unroll
            for (int ma = 0; ma < MA; ma++)
                #pragma unroll
                for (int na = 0; na < NA; na++)
                    mma16816(acc[ma][na], a_hi[ma], b_hi[na]);
        }
    };

    issue_loads(0, 0);
    issue_loads(1, 1);
    for (int ck = 0; ck < NC; ck++) {
        const int s = ck % 3;
        if (ck + 2 < NC) { issue_loads(ck + 2, (ck + 2) % 3); CP_WAIT(2); }
        else if (ck + 1 < NC) { CP_WAIT(1); }
        else { CP_WAIT(0); }
        __syncthreads();
        do_compute(s);
        __syncthreads();
    }

    #pragma unroll
    for (int ma = 0; ma < MA; ma++)
        #pragma unroll
        for (int na = 0; na < NA; na++)
            #pragma unroll
            for (int half = 0; half < 2; half++) {
                const int row = bm + wm + ma * 16 + g + half * 8;
                const int col = bn + wn + na * 8 + t * 2;
                float* dst = out + (size_t)row * C_ + col;
                *(float2*)dst = make_float2(acc[ma][na][half * 2 + 0] + bias[col],
                                            acc[ma][na][half * 2 + 1] + bias[col + 1]);
            }
}

// ---------------- conversion kernels ----------------
__global__ void __launch_bounds__(256) conv_x(const float* __restrict__ s)
{
    int i = blockIdx.x * 256 + threadIdx.x;
    float4 v = ((const float4*)s)[i];
    __half2* hp = (__half2*)g_xh;
    hp[i * 2]     = __halves2half2(__float2half(v.x), __float2half(v.y));
    hp[i * 2 + 1] = __halves2half2(__float2half(v.z), __float2half(v.w));
}

template <int W>
__global__ void __launch_bounds__(256) conv_wT(const float* __restrict__ s)
{
    constexpr int Cc = (W == 0) ? QKVC : C_;
    __half* dh = (W == 0) ? g_wqh : g_wph;

    __shared__ float tbuf[32][33];
    const int tx = threadIdx.x & 31, ty = threadIdx.x >> 5;
    const int c0 = blockIdx.x * 32, r0 = blockIdx.y * 32;
    #pragma unroll
    for (int j = 0; j < 4; j++)
        tbuf[ty + j * 8][tx] = s[(size_t)(r0 + ty + j * 8) * Cc + c0 + tx];
    __syncthreads();
    #pragma unroll
    for (int j = 0; j < 4; j++) {
        int i = ty + j * 8;
        dh[(size_t)(c0 + i) * C_ + r0 + tx] = __float2half(tbuf[tx][i]);
    }
}

// ---------------------------------------------------------------------------
extern "C" void kernel_launch(void* const* d_in, const int* in_sizes, int n_in,
                              void* d_out, int out_size)
{
    const float* x      = (const float*)d_in[0];
    const float* w_qkv  = (const float*)d_in[1];
    const float* w_proj = (const float*)d_in[2];
    const float* b_proj = (const float*)d_in[3];
    float* out  = (float*)d_out;
    float* attn = out + (size_t)M_ * C_;

    cudaFuncSetAttribute(qkv_gemm,  cudaFuncAttributeMaxDynamicSharedMemorySize, QK_SMEM);
    cudaFuncSetAttribute(fa_kernel, cudaFuncAttributeMaxDynamicSharedMemorySize, FA_SMEM);
    cudaFuncSetAttribute(proj_gemm, cudaFuncAttributeMaxDynamicSharedMemorySize, PJ_SMEM);

    // 1) input conversions (plain fp16)
    conv_x<<<M_ * C_ / 1024, 256>>>(x);
    conv_wT<0><<<dim3(QKVC / 32, C_ / 32), 256>>>(w_qkv);
    conv_wT<1><<<dim3(C_ / 32, C_ / 32), 256>>>(w_proj);

    // 2) QKV GEMM (1-term) -> q (scaled), k, vT
    qkv_gemm<<<dim3(QKVC / 128, M_ / 128), 256, QK_SMEM>>>();

    // 3) fused: S -> softmax -> attn fp32 write -> P@V -> ctx fp16
    fa_kernel<<<BH_ * 64, 256, FA_SMEM>>>(attn);

    // 4) out = ctx @ w_proj + bias (1-term)
    proj_gemm<<<dim3(C_ / 128, M_ / 128), 256, PJ_SMEM>>>(out, b_proj);
}

// round 15
// speedup vs baseline: 1.0643x; 1.0643x over previous
#include <cuda_runtime.h>
#include <cuda_fp16.h>

typedef unsigned int u32;

#define B_   8
#define N_   1024
#define C_   1024
#define H_   16
#define D_   64
#define M_   (B_ * N_)     // 8192
#define QKVC 3072
#define BH_  (B_ * H_)     // 128

// ---------------- allocation-free scratch (device globals, fp16) ----------
__device__ __align__(256) __half g_xh[(size_t)M_ * C_];
__device__ __align__(256) __half g_wqh[(size_t)QKVC * C_];
__device__ __align__(256) __half g_wph[(size_t)C_ * C_];
__device__ __align__(256) __half g_qh[(size_t)BH_ * N_ * D_];
__device__ __align__(256) __half g_kh[(size_t)BH_ * N_ * D_];
__device__ __align__(256) __half g_vTh[(size_t)BH_ * D_ * N_];
__device__ __align__(256) __half g_ch[(size_t)M_ * C_];
__device__ __align__(256) __half g_ah[(size_t)BH_ * N_ * N_];   // fp16 P handoff

// ---------------- helpers ----------------
__device__ __forceinline__ u32 smem_u32(const void* p) {
    u32 a;
    asm("{ .reg .u64 t; cvta.to.shared.u64 t, %1; cvt.u32.u64 %0, t; }" : "=r"(a) : "l"(p));
    return a;
}
#define CP16(dst, src) \
    asm volatile("cp.async.cg.shared.global [%0], [%1], 16;" :: "r"(dst), "l"(src) : "memory")
#define CP_COMMIT() asm volatile("cp.async.commit_group;" ::: "memory")
#define CP_WAIT(n)  asm volatile("cp.async.wait_group %0;" :: "n"(n) : "memory")

__device__ __forceinline__ void ldm4(u32& r0, u32& r1, u32& r2, u32& r3, u32 a) {
    asm volatile("ldmatrix.sync.aligned.m8n8.x4.shared.b16 {%0,%1,%2,%3}, [%4];"
        : "=r"(r0), "=r"(r1), "=r"(r2), "=r"(r3) : "r"(a));
}
__device__ __forceinline__ void mma16816(float* c, const u32* a, const u32* b) {
    asm volatile(
        "mma.sync.aligned.m16n8k16.row.col.f32.f16.f16.f32 "
        "{%0,%1,%2,%3}, {%4,%5,%6,%7}, {%8,%9}, {%0,%1,%2,%3};"
        : "+f"(c[0]), "+f"(c[1]), "+f"(c[2]), "+f"(c[3])
        : "r"(a[0]), "r"(a[1]), "r"(a[2]), "r"(a[3]), "r"(b[0]), "r"(b[1]));
}

// ---------------------------------------------------------------------------
// QKV GEMM: 1-term fp16. 256 thr, 2 CTAs/SM, MA4 NA4, 3-stage ring. (r13)
// ---------------------------------------------------------------------------
#define QK_PART  10240
#define QK_STAGE (2 * QK_PART)
#define QK_SMEM  (3 * QK_STAGE)   // 61440

__global__ void __launch_bounds__(256, 2) qkv_gemm()
{
    constexpr int NC = 32;
    constexpr int MA = 4;
    constexpr int NA = 4;

    extern __shared__ char smem[];
    const u32 sb   = smem_u32(smem);
    const int tid  = threadIdx.x;
    const int wid  = tid >> 5, lane = tid & 31;
    const int g    = lane >> 2, t = lane & 3;
    const int bn   = blockIdx.x * 128;
    const int bm   = blockIdx.y * 128;
    const int wm   = (wid & 1) * 64;
    const int wn   = (wid >> 1) * 32;

    const __half *Ah = g_xh + (size_t)bm * C_;
    const __half *Bh = g_wqh + (size_t)bn * C_;

    float acc[MA][NA][4];
    #pragma unroll
    for (int i = 0; i < MA; i++)
        #pragma unroll
        for (int j = 0; j < NA; j++)
            #pragma unroll
            for (int r = 0; r < 4; r++) acc[i][j][r] = 0.0f;

    auto issue_loads = [&](int ck, int s) {
        const int kofs = ck * 32;
        const u32 base = sb + s * QK_STAGE;
        #pragma unroll
        for (int i = tid; i < 128 * 4; i += 256) {
            int r = i >> 2, sgm = i & 3;
            u32 off = (u32)(r * 80 + sgm * 16);
            const size_t go = (size_t)r * C_ + kofs + sgm * 8;
            CP16(base + off,           Ah + go);
            CP16(base + QK_PART + off, Bh + go);
        }
        CP_COMMIT();
    };

    const u32 arow = (u32)((wm + (lane & 15)) * 80 + ((lane >> 4) << 4));
    const u32 brow = (u32)((wn + (lane & 7) + ((lane >> 4) << 3)) * 80 + (((lane >> 3) & 1) << 4));

    auto do_compute = [&](int s) {
        const u32 abase = sb + s * QK_STAGE;
        const u32 bbase = abase + QK_PART;
        #pragma unroll
        for (int ks = 0; ks < 2; ks++) {
            const u32 kb = ks * 32;
            u32 a_hi[MA][4], b_hi[NA][2];
            #pragma unroll
            for (int ma = 0; ma < MA; ma++) {
                u32 ad = abase + arow + ma * 16 * 80 + kb;
                ldm4(a_hi[ma][0], a_hi[ma][1], a_hi[ma][2], a_hi[ma][3], ad);
            }
            #pragma unroll
            for (int p = 0; p < NA / 2; p++) {
                u32 bd = bbase + brow + p * 16 * 80 + kb;
                ldm4(b_hi[2*p][0], b_hi[2*p][1], b_hi[2*p+1][0], b_hi[2*p+1][1], bd);
            }
            #pragma unroll
            for (int ma = 0; ma < MA; ma++)
                #pragma unroll
                for (int na = 0; na < NA; na++)
                    mma16816(acc[ma][na], a_hi[ma], b_hi[na]);
        }
    };

    issue_loads(0, 0);
    issue_loads(1, 1);
    for (int ck = 0; ck < NC; ck++) {
        const int s = ck % 3;
        if (ck + 2 < NC) { issue_loads(ck + 2, (ck + 2) % 3); CP_WAIT(2); }
        else if (ck + 1 < NC) { CP_WAIT(1); }
        else { CP_WAIT(0); }
        __syncthreads();
        do_compute(s);
        __syncthreads();
    }

    #pragma unroll
    for (int ma = 0; ma < MA; ma++)
        #pragma unroll
        for (int na = 0; na < NA; na++)
            #pragma unroll
            for (int half = 0; half < 2; half++) {
                const int row = bm + wm + ma * 16 + g + half * 8;
                const int col = bn + wn + na * 8 + t * 2;
                float v0 = acc[ma][na][half * 2 + 0];
                float v1 = acc[ma][na][half * 2 + 1];

                const int which = col >> 10;
                const int c     = col & 1023;
                const int h     = c >> 6;
                const int d0    = c & 63;
                const int b8    = row >> 10;
                const int n     = row & 1023;
                const int bh    = b8 * H_ + h;
                if (which == 0) {
                    const size_t base = ((size_t)bh * N_ + n) * D_ + d0;
                    *(__half2*)(g_qh + base) =
                        __halves2half2(__float2half(v0 * 0.125f), __float2half(v1 * 0.125f));
                } else if (which == 1) {
                    const size_t base = ((size_t)bh * N_ + n) * D_ + d0;
                    *(__half2*)(g_kh + base) =
                        __halves2half2(__float2half(v0), __float2half(v1));
                } else {
                    const size_t vb = (size_t)bh * D_ * N_ + n;
                    g_vTh[vb + (size_t)d0 * N_]       = __float2half(v0);
                    g_vTh[vb + (size_t)(d0 + 1) * N_] = __float2half(v1);
                }
            }
}

// ---------------------------------------------------------------------------
// S = qh @ kh^T -> softmax -> attn fp32 + P fp16 (g_ah). r13 structure.
// ---------------------------------------------------------------------------
#define Q_OFF  0
#define K_OFF  4608
#define KSTG   18432
#define S_OFF  41472
#define S_PIT  4144
#define SS_SMEM (S_OFF + 32 * S_PIT)   // 174080

__global__ void __launch_bounds__(256, 1) sscore_kernel(float* __restrict__ attn)
{
    extern __shared__ char smem[];
    const u32 sb   = smem_u32(smem);
    const int tid  = threadIdx.x;
    const int wid  = tid >> 5, lane = tid & 31;
    const int g    = lane >> 2, t = lane & 3;

    const int bh   = blockIdx.x >> 5;
    const int row0 = (blockIdx.x & 31) * 32;
    const int wm   = (wid & 1) * 16;
    const int wn   = (wid >> 1) * 32;

    const __half* Qh = g_qh + ((size_t)bh * N_ + row0) * D_;
    const __half* Kh = g_kh + (size_t)bh * N_ * D_;

    {
        int r = tid >> 3, sgm = tid & 7;
        u32 off = (u32)(r * 144 + sgm * 16);
        *(float4*)(smem + Q_OFF + off) = *(const float4*)(Qh + r * D_ + sgm * 8);
    }

    auto issueK = [&](int c, int s) {
        const u32 base = sb + K_OFF + s * KSTG;
        const size_t ko = (size_t)c * 128 * D_;
        #pragma unroll
        for (int i = tid; i < 128 * 8; i += 256) {
            int r = i >> 3, sgm = i & 7;
            CP16(base + (u32)(r * 144 + sgm * 16), Kh + ko + r * D_ + sgm * 8);
        }
        CP_COMMIT();
    };

    const u32 arow = (u32)((wm + (lane & 15)) * 144 + ((lane >> 4) << 4));
    const u32 brow = (u32)((wn + (lane & 7) + ((lane >> 4) << 3)) * 144 + (((lane >> 3) & 1) << 4));

    issueK(0, 0);
    issueK(1, 1);
    for (int c = 0; c < 8; c++) {
        if (c < 7) CP_WAIT(1); else CP_WAIT(0);
        __syncthreads();

        const u32 kb0 = sb + K_OFF + (c & 1) * KSTG;
        float acc[4][4];
        #pragma unroll
        for (int j = 0; j < 4; j++)
            #pragma unroll
            for (int r = 0; r < 4; r++) acc[j][r] = 0.0f;

        #pragma unroll
        for (int ks = 0; ks < 4; ks++) {
            const u32 kb = ks * 32;
            u32 a_hi[4], b_hi[4][2];
            ldm4(a_hi[0], a_hi[1], a_hi[2], a_hi[3], sb + Q_OFF + arow + kb);
            #pragma unroll
            for (int p = 0; p < 2; p++) {
                u32 bd = kb0 + brow + p * 16 * 144 + kb;
                ldm4(b_hi[2*p][0], b_hi[2*p][1], b_hi[2*p+1][0], b_hi[2*p+1][1], bd);
            }
            #pragma unroll
            for (int na = 0; na < 4; na++)
                mma16816(acc[na], a_hi, b_hi[na]);
        }

        #pragma unroll
        for (int na = 0; na < 4; na++)
            #pragma unroll
            for (int half = 0; half < 2; half++) {
                int row = wm + g + half * 8;
                int col = c * 128 + wn + na * 8 + t * 2;
                *(float2*)(smem + S_OFF + row * S_PIT + col * 4) =
                    make_float2(acc[na][half * 2], acc[na][half * 2 + 1]);
            }

        __syncthreads();
        if (c + 2 < 8) issueK(c + 2, c & 1);
    }

    #pragma unroll
    for (int rr = 0; rr < 4; rr++) {
        const int r = wid * 4 + rr;
        const float* Srow = (const float*)(smem + S_OFF + r * S_PIT);
        float4 f[8];
        float m = -1e30f;
        #pragma unroll
        for (int i = 0; i < 8; i++) {
            f[i] = *(const float4*)(Srow + (lane + i * 32) * 4);
            m = fmaxf(m, fmaxf(fmaxf(f[i].x, f[i].y), fmaxf(f[i].z, f[i].w)));
        }
        #pragma unroll
        for (int o = 16; o > 0; o >>= 1) m = fmaxf(m, __shfl_xor_sync(0xffffffffu, m, o));
        float s = 0.0f;
        #pragma unroll
        for (int i = 0; i < 8; i++) {
            f[i].x = __expf(f[i].x - m); f[i].y = __expf(f[i].y - m);
            f[i].z = __expf(f[i].z - m); f[i].w = __expf(f[i].w - m);
            s += f[i].x + f[i].y + f[i].z + f[i].w;
        }
        #pragma unroll
        for (int o = 16; o > 0; o >>= 1) s += __shfl_xor_sync(0xffffffffu, s, o);
        const float inv = 1.0f / s;

        const size_t gr = (size_t)bh * N_ + row0 + r;
        float* ap = attn + gr * N_;
        __half2* php = (__half2*)(g_ah + gr * N_);
        #pragma unroll
        for (int i = 0; i < 8; i++) {
            float4 p = make_float4(f[i].x * inv, f[i].y * inv, f[i].z * inv, f[i].w * inv);
            *(float4*)(ap + (lane + i * 32) * 4) = p;
            const int c2 = (lane + i * 32) * 2;
            php[c2]     = __halves2half2(__float2half(p.x), __float2half(p.y));
            php[c2 + 1] = __halves2half2(__float2half(p.z), __float2half(p.w));
        }
    }
}

// ---------------------------------------------------------------------------
// AV GEMM: ctx = Ph(fp16 from g_ah) @ Vh. No conversion phase. 2 CTAs/SM.
// Smem: A ring 3 x 10240 | V ring 3 x 5120 = 46080.
// ---------------------------------------------------------------------------
#define AV_APART 10240
#define AV_B_OFF (3 * AV_APART)            // 30720
#define AV_BSTG  5120
#define AV_SMEM  (AV_B_OFF + 3 * AV_BSTG)  // 46080

__global__ void __launch_bounds__(256, 2) av_gemm()
{
    extern __shared__ char smem[];
    const u32 sb   = smem_u32(smem);
    const int tid  = threadIdx.x;
    const int wid  = tid >> 5, lane = tid & 31;
    const int g    = lane >> 2, t = lane & 3;

    const int bm = blockIdx.y * 128;
    const int z  = blockIdx.z;
    const int b8 = z >> 4, h = z & 15;
    const int wm = (wid & 3) * 32;
    const int wn = (wid >> 2) * 32;

    const __half* Ap = g_ah + (size_t)z * N_ * N_ + (size_t)bm * N_;
    const __half* Vh = g_vTh + (size_t)z * D_ * N_;

    float acc[2][4][4];
    #pragma unroll
    for (int i = 0; i < 2; i++)
        #pragma unroll
        for (int j = 0; j < 4; j++)
            #pragma unroll
            for (int r = 0; r < 4; r++) acc[i][j][r] = 0.0f;

    auto issue_loads = [&](int ck, int s) {
        const int kofs = ck * 32;
        const u32 abase = sb + s * AV_APART;
        #pragma unroll
        for (int i = tid; i < 128 * 4; i += 256) {
            int r = i >> 2, sgm = i & 3;
            CP16(abase + (u32)(r * 80 + sgm * 16), Ap + (size_t)r * N_ + kofs + sgm * 8);
        }
        const u32 bbase = sb + AV_B_OFF + s * AV_BSTG;
        #pragma unroll
        for (int i = tid; i < 64 * 4; i += 256) {
            int r = i >> 2, sgm = i & 3;
            CP16(bbase + (u32)(r * 80 + sgm * 16), Vh + (size_t)r * N_ + kofs + sgm * 8);
        }
        CP_COMMIT();
    };

    const u32 arow = (u32)((wm + (lane & 15)) * 80 + ((lane >> 4) << 4));
    const u32 brow = (u32)((wn + (lane & 7) + ((lane >> 4) << 3)) * 80 + (((lane >> 3) & 1) << 4));

    issue_loads(0, 0);
    issue_loads(1, 1);
    for (int ck = 0; ck < 32; ck++) {
        const int s = ck % 3;
        if (ck + 2 < 32) { issue_loads(ck + 2, (ck + 2) % 3); CP_WAIT(2); }
        else if (ck + 1 < 32) { CP_WAIT(1); }
        else { CP_WAIT(0); }
        __syncthreads();

        const u32 ah0 = sb + s * AV_APART;
        const u32 bb0 = sb + AV_B_OFF + s * AV_BSTG;
        #pragma unroll
        for (int ks = 0; ks < 2; ks++) {
            const u32 kb = ks * 32;
            u32 a_hi[2][4], b_hi[4][2];
            #pragma unroll
            for (int ma = 0; ma < 2; ma++) {
                u32 ad = ah0 + arow + ma * 16 * 80 + kb;
                ldm4(a_hi[ma][0], a_hi[ma][1], a_hi[ma][2], a_hi[ma][3], ad);
            }
            #pragma unroll
            for (int p = 0; p < 2; p++) {
                u32 bd = bb0 + brow + p * 16 * 80 + kb;
                ldm4(b_hi[2*p][0], b_hi[2*p][1], b_hi[2*p+1][0], b_hi[2*p+1][1], bd);
            }
            #pragma unroll
            for (int ma = 0; ma < 2; ma++)
                #pragma unroll
                for (int na = 0; na < 4; na++)
                    mma16816(acc[ma][na], a_hi[ma], b_hi[na]);
        }
        __syncthreads();
    }

    #pragma unroll
    for (int ma = 0; ma < 2; ma++)
        #pragma unroll
        for (int na = 0; na < 4; na++)
            #pragma unroll
            for (int half = 0; half < 2; half++) {
                const int row = bm + wm + ma * 16 + g + half * 8;
                const int col = wn + na * 8 + t * 2;
                const size_t base = ((size_t)(b8 * N_ + row)) * C_ + h * 64 + col;
                *(__half2*)(g_ch + base) =
                    __halves2half2(__float2half(acc[ma][na][half * 2 + 0]),
                                   __float2half(acc[ma][na][half * 2 + 1]));
            }
}

// ---------------------------------------------------------------------------
// Projection GEMM: out = ch @ wph + bias. 2 CTAs/SM. (r13)
// ---------------------------------------------------------------------------
#define PJ_PART  10240
#define PJ_STAGE (2 * PJ_PART)
#define PJ_SMEM  (3 * PJ_STAGE)   // 61440

__global__ void __launch_bounds__(256, 2) proj_gemm(float* __restrict__ out,
                                                    const float* __restrict__ bias)
{
    constexpr int NC = 32;
    constexpr int MA = 4;
    constexpr int NA = 4;

    extern __shared__ char smem[];
    const u32 sb   = smem_u32(smem);
    const int tid  = threadIdx.x;
    const int wid  = tid >> 5, lane = tid & 31;
    const int g    = lane >> 2, t = lane & 3;
    const int bn   = blockIdx.x * 128;
    const int bm   = blockIdx.y * 128;
    const int wm   = (wid & 1) * 64;
    const int wn   = (wid >> 1) * 32;

    const __half *Ah = g_ch + (size_t)bm * C_;
    const __half *Bh = g_wph + (size_t)bn * C_;

    float acc[MA][NA][4];
    #pragma unroll
    for (int i = 0; i < MA; i++)
        #pragma unroll
        for (int j = 0; j < NA; j++)
            #pragma unroll
            for (int r = 0; r < 4; r++) acc[i][j][r] = 0.0f;

    auto issue_loads = [&](int ck, int s) {
        const int kofs = ck * 32;
        const u32 base = sb + s * PJ_STAGE;
        #pragma unroll
        for (int i = tid; i < 128 * 4; i += 256) {
            int r = i >> 2, sgm = i & 3;
            u32 off = (u32)(r * 80 + sgm * 16);
            const size_t go = (size_t)r * C_ + kofs + sgm * 8;
            CP16(base + off,           Ah + go);
            CP16(base + PJ_PART + off, Bh + go);
        }
        CP_COMMIT();
    };

    const u32 arow = (u32)((wm + (lane & 15)) * 80 + ((lane >> 4) << 4));
    const u32 brow = (u32)((wn + (lane & 7) + ((lane >> 4) << 3)) * 80 + (((lane >> 3) & 1) << 4));

    auto do_compute = [&](int s) {
        const u32 abase = sb + s * PJ_STAGE;
        const u32 bbase = abase + PJ_PART;
        #pragma unroll
        for (int ks = 0; ks < 2; ks++) {
            const u32 kb = ks * 32;
            u32 a_hi[MA][4], b_hi[NA][2];
            #pragma unroll
            for (int ma = 0; ma < MA; ma++) {
                u32 ad = abase + arow + ma * 16 * 80 + kb;
                ldm4(a_hi[ma][0], a_hi[ma][1], a_hi[ma][2], a_hi[ma][3], ad);
            }
            #pragma unroll
            for (int p = 0; p < NA / 2; p++) {
                u32 bd = bbase + brow + p * 16 * 80 + kb;
                ldm4(b_hi[2*p][0], b_hi[2*p][1], b_hi[2*p+1][0], b_hi[2*p+1][1], bd);
            }
            #pragma unroll
            for (int ma = 0; ma < MA; ma++)
                #pragma unroll
                for (int na = 0; na < NA; na++)
                    mma16816(acc[ma][na], a_hi[ma], b_hi[na]);
        }
    };

    issue_loads(0, 0);
    issue_loads(1, 1);
    for (int ck = 0; ck < NC; ck++) {
        const int s = ck % 3;
        if (ck + 2 < NC) { issue_loads(ck + 2, (ck + 2) % 3); CP_WAIT(2); }
        else if (ck + 1 < NC) { CP_WAIT(1); }
        else { CP_WAIT(0); }
        __syncthreads();
        do_compute(s);
        __syncthreads();
    }

    #pragma unroll
    for (int ma = 0; ma < MA; ma++)
        #pragma unroll
        for (int na = 0; na < NA; na++)
            #pragma unroll
            for (int half = 0; half < 2; half++) {
                const int row = bm + wm + ma * 16 + g + half * 8;
                const int col = bn + wn + na * 8 + t * 2;
                float* dst = out + (size_t)row * C_ + col;
                *(float2*)dst = make_float2(acc[ma][na][half * 2 + 0] + bias[col],
                                            acc[ma][na][half * 2 + 1] + bias[col + 1]);
            }
}

// ---------------- conversion kernels ----------------
__global__ void __launch_bounds__(256) conv_x(const float* __restrict__ s)
{
    int i = blockIdx.x * 256 + threadIdx.x;
    float4 v = ((const float4*)s)[i];
    __half2* hp = (__half2*)g_xh;
    hp[i * 2]     = __halves2half2(__float2half(v.x), __float2half(v.y));
    hp[i * 2 + 1] = __halves2half2(__float2half(v.z), __float2half(v.w));
}

template <int W>
__global__ void __launch_bounds__(256) conv_wT(const float* __restrict__ s)
{
    constexpr int Cc = (W == 0) ? QKVC : C_;
    __half* dh = (W == 0) ? g_wqh : g_wph;

    __shared__ float tbuf[32][33];
    const int tx = threadIdx.x & 31, ty = threadIdx.x >> 5;
    const int c0 = blockIdx.x * 32, r0 = blockIdx.y * 32;
    #pragma unroll
    for (int j = 0; j < 4; j++)
        tbuf[ty + j * 8][tx] = s[(size_t)(r0 + ty + j * 8) * Cc + c0 + tx];
    __syncthreads();
    #pragma unroll
    for (int j = 0; j < 4; j++) {
        int i = ty + j * 8;
        dh[(size_t)(c0 + i) * C_ + r0 + tx] = __float2half(tbuf[tx][i]);
    }
}

// ---------------------------------------------------------------------------
extern "C" void kernel_launch(void* const* d_in, const int* in_sizes, int n_in,
                              void* d_out, int out_size)
{
    const float* x      = (const float*)d_in[0];
    const float* w_qkv  = (const float*)d_in[1];
    const float* w_proj = (const float*)d_in[2];
    const float* b_proj = (const float*)d_in[3];
    float* out  = (float*)d_out;
    float* attn = out + (size_t)M_ * C_;

    cudaFuncSetAttribute(qkv_gemm,      cudaFuncAttributeMaxDynamicSharedMemorySize, QK_SMEM);
    cudaFuncSetAttribute(sscore_kernel, cudaFuncAttributeMaxDynamicSharedMemorySize, SS_SMEM);
    cudaFuncSetAttribute(av_gemm,       cudaFuncAttributeMaxDynamicSharedMemorySize, AV_SMEM);
    cudaFuncSetAttribute(proj_gemm,     cudaFuncAttributeMaxDynamicSharedMemorySize, PJ_SMEM);

    // 1) input conversions (plain fp16)
    conv_x<<<M_ * C_ / 1024, 256>>>(x);
    conv_wT<0><<<dim3(QKVC / 32, C_ / 32), 256>>>(w_qkv);
    conv_wT<1><<<dim3(C_ / 32, C_ / 32), 256>>>(w_proj);

    // 2) QKV GEMM (1-term) -> q (scaled), k, vT
    qkv_gemm<<<dim3(QKVC / 128, M_ / 128), 256, QK_SMEM>>>();

    // 3) S + softmax -> attn fp32 + P fp16 (g_ah)
    sscore_kernel<<<BH_ * 32, 256, SS_SMEM>>>(attn);

    // 4) ctx = P(fp16) @ Vh
    av_gemm<<<dim3(1, N_ / 128, BH_), 256, AV_SMEM>>>();

    // 5) out = ctx @ w_proj + bias
    proj_gemm<<<dim3(C_ / 128, M_ / 128), 256, PJ_SMEM>>>(out, b_proj);
}

// round 16
// speedup vs baseline: 1.1672x; 1.0966x over previous
#include <cuda_runtime.h>
#include <cuda_fp16.h>

typedef unsigned int u32;

#define B_   8
#define N_   1024
#define C_   1024
#define H_   16
#define D_   64
#define M_   (B_ * N_)     // 8192
#define QKVC 3072
#define BH_  (B_ * H_)     // 128

// ---------------- allocation-free scratch (device globals, fp16) ----------
__device__ __align__(256) __half g_xh[(size_t)M_ * C_];
__device__ __align__(256) __half g_wqh[(size_t)QKVC * C_];
__device__ __align__(256) __half g_wph[(size_t)C_ * C_];
__device__ __align__(256) __half g_qh[(size_t)BH_ * N_ * D_];
__device__ __align__(256) __half g_kh[(size_t)BH_ * N_ * D_];
__device__ __align__(256) __half g_vTh[(size_t)BH_ * D_ * N_];
__device__ __align__(256) __half g_ch[(size_t)M_ * C_];
__device__ __align__(256) __half g_ah[(size_t)BH_ * N_ * N_];   // fp16 P handoff

// ---------------- helpers ----------------
__device__ __forceinline__ u32 smem_u32(const void* p) {
    u32 a;
    asm("{ .reg .u64 t; cvta.to.shared.u64 t, %1; cvt.u32.u64 %0, t; }" : "=r"(a) : "l"(p));
    return a;
}
#define CP16(dst, src) \
    asm volatile("cp.async.cg.shared.global [%0], [%1], 16;" :: "r"(dst), "l"(src) : "memory")
#define CP_COMMIT() asm volatile("cp.async.commit_group;" ::: "memory")
#define CP_WAIT(n)  asm volatile("cp.async.wait_group %0;" :: "n"(n) : "memory")

__device__ __forceinline__ void ldm4(u32& r0, u32& r1, u32& r2, u32& r3, u32 a) {
    asm volatile("ldmatrix.sync.aligned.m8n8.x4.shared.b16 {%0,%1,%2,%3}, [%4];"
        : "=r"(r0), "=r"(r1), "=r"(r2), "=r"(r3) : "r"(a));
}
__device__ __forceinline__ void mma16816(float* c, const u32* a, const u32* b) {
    asm volatile(
        "mma.sync.aligned.m16n8k16.row.col.f32.f16.f16.f32 "
        "{%0,%1,%2,%3}, {%4,%5,%6,%7}, {%8,%9}, {%0,%1,%2,%3};"
        : "+f"(c[0]), "+f"(c[1]), "+f"(c[2]), "+f"(c[3])
        : "r"(a[0]), "r"(a[1]), "r"(a[2]), "r"(a[3]), "r"(b[0]), "r"(b[1]));
}

// ---------------------------------------------------------------------------
// QKV GEMM: 1-term fp16. 256 thr, 2 CTAs/SM, MA4 NA4, 3-stage ring. (r13)
// ---------------------------------------------------------------------------
#define QK_PART  10240
#define QK_STAGE (2 * QK_PART)
#define QK_SMEM  (3 * QK_STAGE)   // 61440

__global__ void __launch_bounds__(256, 2) qkv_gemm()
{
    constexpr int NC = 32;
    constexpr int MA = 4;
    constexpr int NA = 4;

    extern __shared__ char smem[];
    const u32 sb   = smem_u32(smem);
    const int tid  = threadIdx.x;
    const int wid  = tid >> 5, lane = tid & 31;
    const int g    = lane >> 2, t = lane & 3;
    const int bn   = blockIdx.x * 128;
    const int bm   = blockIdx.y * 128;
    const int wm   = (wid & 1) * 64;
    const int wn   = (wid >> 1) * 32;

    const __half *Ah = g_xh + (size_t)bm * C_;
    const __half *Bh = g_wqh + (size_t)bn * C_;

    float acc[MA][NA][4];
    #pragma unroll
    for (int i = 0; i < MA; i++)
        #pragma unroll
        for (int j = 0; j < NA; j++)
            #pragma unroll
            for (int r = 0; r < 4; r++) acc[i][j][r] = 0.0f;

    auto issue_loads = [&](int ck, int s) {
        const int kofs = ck * 32;
        const u32 base = sb + s * QK_STAGE;
        #pragma unroll
        for (int i = tid; i < 128 * 4; i += 256) {
            int r = i >> 2, sgm = i & 3;
            u32 off = (u32)(r * 80 + sgm * 16);
            const size_t go = (size_t)r * C_ + kofs + sgm * 8;
            CP16(base + off,           Ah + go);
            CP16(base + QK_PART + off, Bh + go);
        }
        CP_COMMIT();
    };

    const u32 arow = (u32)((wm + (lane & 15)) * 80 + ((lane >> 4) << 4));
    const u32 brow = (u32)((wn + (lane & 7) + ((lane >> 4) << 3)) * 80 + (((lane >> 3) & 1) << 4));

    auto do_compute = [&](int s) {
        const u32 abase = sb + s * QK_STAGE;
        const u32 bbase = abase + QK_PART;
        #pragma unroll
        for (int ks = 0; ks < 2; ks++) {
            const u32 kb = ks * 32;
            u32 a_hi[MA][4], b_hi[NA][2];
            #pragma unroll
            for (int ma = 0; ma < MA; ma++) {
                u32 ad = abase + arow + ma * 16 * 80 + kb;
                ldm4(a_hi[ma][0], a_hi[ma][1], a_hi[ma][2], a_hi[ma][3], ad);
            }
            #pragma unroll
            for (int p = 0; p < NA / 2; p++) {
                u32 bd = bbase + brow + p * 16 * 80 + kb;
                ldm4(b_hi[2*p][0], b_hi[2*p][1], b_hi[2*p+1][0], b_hi[2*p+1][1], bd);
            }
            #pragma unroll
            for (int ma = 0; ma < MA; ma++)
                #pragma unroll
                for (int na = 0; na < NA; na++)
                    mma16816(acc[ma][na], a_hi[ma], b_hi[na]);
        }
    };

    issue_loads(0, 0);
    issue_loads(1, 1);
    for (int ck = 0; ck < NC; ck++) {
        const int s = ck % 3;
        if (ck + 2 < NC) { issue_loads(ck + 2, (ck + 2) % 3); CP_WAIT(2); }
        else if (ck + 1 < NC) { CP_WAIT(1); }
        else { CP_WAIT(0); }
        __syncthreads();
        do_compute(s);
        __syncthreads();
    }

    #pragma unroll
    for (int ma = 0; ma < MA; ma++)
        #pragma unroll
        for (int na = 0; na < NA; na++)
            #pragma unroll
            for (int half = 0; half < 2; half++) {
                const int row = bm + wm + ma * 16 + g + half * 8;
                const int col = bn + wn + na * 8 + t * 2;
                float v0 = acc[ma][na][half * 2 + 0];
                float v1 = acc[ma][na][half * 2 + 1];

                const int which = col >> 10;
                const int c     = col & 1023;
                const int h     = c >> 6;
                const int d0    = c & 63;
                const int b8    = row >> 10;
                const int n     = row & 1023;
                const int bh    = b8 * H_ + h;
                if (which == 0) {
                    const size_t base = ((size_t)bh * N_ + n) * D_ + d0;
                    *(__half2*)(g_qh + base) =
                        __halves2half2(__float2half(v0 * 0.125f), __float2half(v1 * 0.125f));
                } else if (which == 1) {
                    const size_t base = ((size_t)bh * N_ + n) * D_ + d0;
                    *(__half2*)(g_kh + base) =
                        __halves2half2(__float2half(v0), __float2half(v1));
                } else {
                    const size_t vb = (size_t)bh * D_ * N_ + n;
                    g_vTh[vb + (size_t)d0 * N_]       = __float2half(v0);
                    g_vTh[vb + (size_t)(d0 + 1) * N_] = __float2half(v1);
                }
            }
}

// ---------------------------------------------------------------------------
// S = qh @ kh^T (scores stored fp16 in smem) -> softmax -> attn fp32 + P fp16.
// S buffer 32 x 2080 B = 66560 -> total 108 KB -> 2 CTAs/SM.
// ---------------------------------------------------------------------------
#define Q_OFF   0
#define K_OFF   4608
#define KSTG    18432
#define S_OFF   41472
#define S_PIT2  2080
#define SS_SMEM (S_OFF + 32 * S_PIT2)   // 108032

__global__ void __launch_bounds__(256, 2) sscore_kernel(float* __restrict__ attn)
{
    extern __shared__ char smem[];
    const u32 sb   = smem_u32(smem);
    const int tid  = threadIdx.x;
    const int wid  = tid >> 5, lane = tid & 31;
    const int g    = lane >> 2, t = lane & 3;

    const int bh   = blockIdx.x >> 5;
    const int row0 = (blockIdx.x & 31) * 32;
    const int wm   = (wid & 1) * 16;
    const int wn   = (wid >> 1) * 32;

    const __half* Qh = g_qh + ((size_t)bh * N_ + row0) * D_;
    const __half* Kh = g_kh + (size_t)bh * N_ * D_;

    {
        int r = tid >> 3, sgm = tid & 7;
        u32 off = (u32)(r * 144 + sgm * 16);
        *(float4*)(smem + Q_OFF + off) = *(const float4*)(Qh + r * D_ + sgm * 8);
    }

    auto issueK = [&](int c, int s) {
        const u32 base = sb + K_OFF + s * KSTG;
        const size_t ko = (size_t)c * 128 * D_;
        #pragma unroll
        for (int i = tid; i < 128 * 8; i += 256) {
            int r = i >> 3, sgm = i & 7;
            CP16(base + (u32)(r * 144 + sgm * 16), Kh + ko + r * D_ + sgm * 8);
        }
        CP_COMMIT();
    };

    const u32 arow = (u32)((wm + (lane & 15)) * 144 + ((lane >> 4) << 4));
    const u32 brow = (u32)((wn + (lane & 7) + ((lane >> 4) << 3)) * 144 + (((lane >> 3) & 1) << 4));

    issueK(0, 0);
    issueK(1, 1);
    for (int c = 0; c < 8; c++) {
        if (c < 7) CP_WAIT(1); else CP_WAIT(0);
        __syncthreads();

        const u32 kb0 = sb + K_OFF + (c & 1) * KSTG;
        float acc[4][4];
        #pragma unroll
        for (int j = 0; j < 4; j++)
            #pragma unroll
            for (int r = 0; r < 4; r++) acc[j][r] = 0.0f;

        #pragma unroll
        for (int ks = 0; ks < 4; ks++) {
            const u32 kb = ks * 32;
            u32 a_hi[4], b_hi[4][2];
            ldm4(a_hi[0], a_hi[1], a_hi[2], a_hi[3], sb + Q_OFF + arow + kb);
            #pragma unroll
            for (int p = 0; p < 2; p++) {
                u32 bd = kb0 + brow + p * 16 * 144 + kb;
                ldm4(b_hi[2*p][0], b_hi[2*p][1], b_hi[2*p+1][0], b_hi[2*p+1][1], bd);
            }
            #pragma unroll
            for (int na = 0; na < 4; na++)
                mma16816(acc[na], a_hi, b_hi[na]);
        }

        // store scores as fp16
        #pragma unroll
        for (int na = 0; na < 4; na++)
            #pragma unroll
            for (int half = 0; half < 2; half++) {
                int row = wm + g + half * 8;
                int col = c * 128 + wn + na * 8 + t * 2;
                *(__half2*)(smem + S_OFF + row * S_PIT2 + col * 2) =
                    __halves2half2(__float2half(acc[na][half * 2]),
                                   __float2half(acc[na][half * 2 + 1]));
            }

        __syncthreads();
        if (c + 2 < 8) issueK(c + 2, c & 1);
    }

    // ---- softmax (4 rows/warp) from fp16 scores -> attn fp32 + P fp16 ----
    #pragma unroll
    for (int rr = 0; rr < 4; rr++) {
        const int r = wid * 4 + rr;
        const char* Srow = smem + S_OFF + r * S_PIT2;
        float f[4][8];
        float m = -1e30f;
        #pragma unroll
        for (int i = 0; i < 4; i++) {
            uint4 raw = *(const uint4*)(Srow + lane * 16 + i * 512);
            const u32 w[4] = { raw.x, raw.y, raw.z, raw.w };
            #pragma unroll
            for (int j = 0; j < 4; j++) {
                float2 v = __half22float2(*(const __half2*)&w[j]);
                f[i][2*j]   = v.x;
                f[i][2*j+1] = v.y;
                m = fmaxf(m, fmaxf(v.x, v.y));
            }
        }
        #pragma unroll
        for (int o = 16; o > 0; o >>= 1) m = fmaxf(m, __shfl_xor_sync(0xffffffffu, m, o));
        float s = 0.0f;
        #pragma unroll
        for (int i = 0; i < 4; i++)
            #pragma unroll
            for (int j = 0; j < 8; j++) {
                f[i][j] = __expf(f[i][j] - m);
                s += f[i][j];
            }
        #pragma unroll
        for (int o = 16; o > 0; o >>= 1) s += __shfl_xor_sync(0xffffffffu, s, o);
        const float inv = 1.0f / s;

        const size_t gr = (size_t)bh * N_ + row0 + r;
        float* ap = attn + gr * N_;
        __half* php = g_ah + gr * N_;
        #pragma unroll
        for (int i = 0; i < 4; i++) {
            const int c0 = lane * 8 + i * 256;
            float p[8];
            #pragma unroll
            for (int j = 0; j < 8; j++) p[j] = f[i][j] * inv;
            *(float4*)(ap + c0)     = make_float4(p[0], p[1], p[2], p[3]);
            *(float4*)(ap + c0 + 4) = make_float4(p[4], p[5], p[6], p[7]);
            __half2 h0 = __halves2half2(__float2half(p[0]), __float2half(p[1]));
            __half2 h1 = __halves2half2(__float2half(p[2]), __float2half(p[3]));
            __half2 h2 = __halves2half2(__float2half(p[4]), __float2half(p[5]));
            __half2 h3 = __halves2half2(__float2half(p[6]), __float2half(p[7]));
            *(uint4*)(php + c0) = make_uint4(*(u32*)&h0, *(u32*)&h1, *(u32*)&h2, *(u32*)&h3);
        }
    }
}

// ---------------------------------------------------------------------------
// AV GEMM: ctx = Ph(fp16 from g_ah) @ Vh. 2 CTAs/SM. (r15)
// ---------------------------------------------------------------------------
#define AV_APART 10240
#define AV_B_OFF (3 * AV_APART)            // 30720
#define AV_BSTG  5120
#define AV_SMEM  (AV_B_OFF + 3 * AV_BSTG)  // 46080

__global__ void __launch_bounds__(256, 2) av_gemm()
{
    extern __shared__ char smem[];
    const u32 sb   = smem_u32(smem);
    const int tid  = threadIdx.x;
    const int wid  = tid >> 5, lane = tid & 31;
    const int g    = lane >> 2, t = lane & 3;

    const int bm = blockIdx.y * 128;
    const int z  = blockIdx.z;
    const int b8 = z >> 4, h = z & 15;
    const int wm = (wid & 3) * 32;
    const int wn = (wid >> 2) * 32;

    const __half* Ap = g_ah + (size_t)z * N_ * N_ + (size_t)bm * N_;
    const __half* Vh = g_vTh + (size_t)z * D_ * N_;

    float acc[2][4][4];
    #pragma unroll
    for (int i = 0; i < 2; i++)
        #pragma unroll
        for (int j = 0; j < 4; j++)
            #pragma unroll
            for (int r = 0; r < 4; r++) acc[i][j][r] = 0.0f;

    auto issue_loads = [&](int ck, int s) {
        const int kofs = ck * 32;
        const u32 abase = sb + s * AV_APART;
        #pragma unroll
        for (int i = tid; i < 128 * 4; i += 256) {
            int r = i >> 2, sgm = i & 3;
            CP16(abase + (u32)(r * 80 + sgm * 16), Ap + (size_t)r * N_ + kofs + sgm * 8);
        }
        const u32 bbase = sb + AV_B_OFF + s * AV_BSTG;
        #pragma unroll
        for (int i = tid; i < 64 * 4; i += 256) {
            int r = i >> 2, sgm = i & 3;
            CP16(bbase + (u32)(r * 80 + sgm * 16), Vh + (size_t)r * N_ + kofs + sgm * 8);
        }
        CP_COMMIT();
    };

    const u32 arow = (u32)((wm + (lane & 15)) * 80 + ((lane >> 4) << 4));
    const u32 brow = (u32)((wn + (lane & 7) + ((lane >> 4) << 3)) * 80 + (((lane >> 3) & 1) << 4));

    issue_loads(0, 0);
    issue_loads(1, 1);
    for (int ck = 0; ck < 32; ck++) {
        const int s = ck % 3;
        if (ck + 2 < 32) { issue_loads(ck + 2, (ck + 2) % 3); CP_WAIT(2); }
        else if (ck + 1 < 32) { CP_WAIT(1); }
        else { CP_WAIT(0); }
        __syncthreads();

        const u32 ah0 = sb + s * AV_APART;
        const u32 bb0 = sb + AV_B_OFF + s * AV_BSTG;
        #pragma unroll
        for (int ks = 0; ks < 2; ks++) {
            const u32 kb = ks * 32;
            u32 a_hi[2][4], b_hi[4][2];
            #pragma unroll
            for (int ma = 0; ma < 2; ma++) {
                u32 ad = ah0 + arow + ma * 16 * 80 + kb;
                ldm4(a_hi[ma][0], a_hi[ma][1], a_hi[ma][2], a_hi[ma][3], ad);
            }
            #pragma unroll
            for (int p = 0; p < 2; p++) {
                u32 bd = bb0 + brow + p * 16 * 80 + kb;
                ldm4(b_hi[2*p][0], b_hi[2*p][1], b_hi[2*p+1][0], b_hi[2*p+1][1], bd);
            }
            #pragma unroll
            for (int ma = 0; ma < 2; ma++)
                #pragma unroll
                for (int na = 0; na < 4; na++)
                    mma16816(acc[ma][na], a_hi[ma], b_hi[na]);
        }
        __syncthreads();
    }

    #pragma unroll
    for (int ma = 0; ma < 2; ma++)
        #pragma unroll
        for (int na = 0; na < 4; na++)
            #pragma unroll
            for (int half = 0; half < 2; half++) {
                const int row = bm + wm + ma * 16 + g + half * 8;
                const int col = wn + na * 8 + t * 2;
                const size_t base = ((size_t)(b8 * N_ + row)) * C_ + h * 64 + col;
                *(__half2*)(g_ch + base) =
                    __halves2half2(__float2half(acc[ma][na][half * 2 + 0]),
                                   __float2half(acc[ma][na][half * 2 + 1]));
            }
}

// ---------------------------------------------------------------------------
// Projection GEMM: out = ch @ wph + bias. 2 CTAs/SM. (r13)
// ---------------------------------------------------------------------------
#define PJ_PART  10240
#define PJ_STAGE (2 * PJ_PART)
#define PJ_SMEM  (3 * PJ_STAGE)   // 61440

__global__ void __launch_bounds__(256, 2) proj_gemm(float* __restrict__ out,
                                                    const float* __restrict__ bias)
{
    constexpr int NC = 32;
    constexpr int MA = 4;
    constexpr int NA = 4;

    extern __shared__ char smem[];
    const u32 sb   = smem_u32(smem);
    const int tid  = threadIdx.x;
    const int wid  = tid >> 5, lane = tid & 31;
    const int g    = lane >> 2, t = lane & 3;
    const int bn   = blockIdx.x * 128;
    const int bm   = blockIdx.y * 128;
    const int wm   = (wid & 1) * 64;
    const int wn   = (wid >> 1) * 32;

    const __half *Ah = g_ch + (size_t)bm * C_;
    const __half *Bh = g_wph + (size_t)bn * C_;

    float acc[MA][NA][4];
    #pragma unroll
    for (int i = 0; i < MA; i++)
        #pragma unroll
        for (int j = 0; j < NA; j++)
            #pragma unroll
            for (int r = 0; r < 4; r++) acc[i][j][r] = 0.0f;

    auto issue_loads = [&](int ck, int s) {
        const int kofs = ck * 32;
        const u32 base = sb + s * PJ_STAGE;
        #pragma unroll
        for (int i = tid; i < 128 * 4; i += 256) {
            int r = i >> 2, sgm = i & 3;
            u32 off = (u32)(r * 80 + sgm * 16);
            const size_t go = (size_t)r * C_ + kofs + sgm * 8;
            CP16(base + off,           Ah + go);
            CP16(base + PJ_PART + off, Bh + go);
        }
        CP_COMMIT();
    };

    const u32 arow = (u32)((wm + (lane & 15)) * 80 + ((lane >> 4) << 4));
    const u32 brow = (u32)((wn + (lane & 7) + ((lane >> 4) << 3)) * 80 + (((lane >> 3) & 1) << 4));

    auto do_compute = [&](int s) {
        const u32 abase = sb + s * PJ_STAGE;
        const u32 bbase = abase + PJ_PART;
        #pragma unroll
        for (int ks = 0; ks < 2; ks++) {
            const u32 kb = ks * 32;
            u32 a_hi[MA][4], b_hi[NA][2];
            #pragma unroll
            for (int ma = 0; ma < MA; ma++) {
                u32 ad = abase + arow + ma * 16 * 80 + kb;
                ldm4(a_hi[ma][0], a_hi[ma][1], a_hi[ma][2], a_hi[ma][3], ad);
            }
            #pragma unroll
            for (int p = 0; p < NA / 2; p++) {
                u32 bd = bbase + brow + p * 16 * 80 + kb;
                ldm4(b_hi[2*p][0], b_hi[2*p][1], b_hi[2*p+1][0], b_hi[2*p+1][1], bd);
            }
            #pragma unroll
            for (int ma = 0; ma < MA; ma++)
                #pragma unroll
                for (int na = 0; na < NA; na++)
                    mma16816(acc[ma][na], a_hi[ma], b_hi[na]);
        }
    };

    issue_loads(0, 0);
    issue_loads(1, 1);
    for (int ck = 0; ck < NC; ck++) {
        const int s = ck % 3;
        if (ck + 2 < NC) { issue_loads(ck + 2, (ck + 2) % 3); CP_WAIT(2); }
        else if (ck + 1 < NC) { CP_WAIT(1); }
        else { CP_WAIT(0); }
        __syncthreads();
        do_compute(s);
        __syncthreads();
    }

    #pragma unroll
    for (int ma = 0; ma < MA; ma++)
        #pragma unroll
        for (int na = 0; na < NA; na++)
            #pragma unroll
            for (int half = 0; half < 2; half++) {
                const int row = bm + wm + ma * 16 + g + half * 8;
                const int col = bn + wn + na * 8 + t * 2;
                float* dst = out + (size_t)row * C_ + col;
                *(float2*)dst = make_float2(acc[ma][na][half * 2 + 0] + bias[col],
                                            acc[ma][na][half * 2 + 1] + bias[col + 1]);
            }
}

// ---------------- conversion kernels ----------------
__global__ void __launch_bounds__(256) conv_x(const float* __restrict__ s)
{
    int i = blockIdx.x * 256 + threadIdx.x;
    float4 v = ((const float4*)s)[i];
    __half2* hp = (__half2*)g_xh;
    hp[i * 2]     = __halves2half2(__float2half(v.x), __float2half(v.y));
    hp[i * 2 + 1] = __halves2half2(__float2half(v.z), __float2half(v.w));
}

template <int W>
__global__ void __launch_bounds__(256) conv_wT(const float* __restrict__ s)
{
    constexpr int Cc = (W == 0) ? QKVC : C_;
    __half* dh = (W == 0) ? g_wqh : g_wph;

    __shared__ float tbuf[32][33];
    const int tx = threadIdx.x & 31, ty = threadIdx.x >> 5;
    const int c0 = blockIdx.x * 32, r0 = blockIdx.y * 32;
    #pragma unroll
    for (int j = 0; j < 4; j++)
        tbuf[ty + j * 8][tx] = s[(size_t)(r0 + ty + j * 8) * Cc + c0 + tx];
    __syncthreads();
    #pragma unroll
    for (int j = 0; j < 4; j++) {
        int i = ty + j * 8;
        dh[(size_t)(c0 + i) * C_ + r0 + tx] = __float2half(tbuf[tx][i]);
    }
}

// ---------------------------------------------------------------------------
extern "C" void kernel_launch(void* const* d_in, const int* in_sizes, int n_in,
                              void* d_out, int out_size)
{
    const float* x      = (const float*)d_in[0];
    const float* w_qkv  = (const float*)d_in[1];
    const float* w_proj = (const float*)d_in[2];
    const float* b_proj = (const float*)d_in[3];
    float* out  = (float*)d_out;
    float* attn = out + (size_t)M_ * C_;

    cudaFuncSetAttribute(qkv_gemm,      cudaFuncAttributeMaxDynamicSharedMemorySize, QK_SMEM);
    cudaFuncSetAttribute(sscore_kernel, cudaFuncAttributeMaxDynamicSharedMemorySize, SS_SMEM);
    cudaFuncSetAttribute(av_gemm,       cudaFuncAttributeMaxDynamicSharedMemorySize, AV_SMEM);
    cudaFuncSetAttribute(proj_gemm,     cudaFuncAttributeMaxDynamicSharedMemorySize, PJ_SMEM);

    // 1) input conversions (plain fp16)
    conv_x<<<M_ * C_ / 1024, 256>>>(x);
    conv_wT<0><<<dim3(QKVC / 32, C_ / 32), 256>>>(w_qkv);
    conv_wT<1><<<dim3(C_ / 32, C_ / 32), 256>>>(w_proj);

    // 2) QKV GEMM (1-term) -> q (scaled), k, vT
    qkv_gemm<<<dim3(QKVC / 128, M_ / 128), 256, QK_SMEM>>>();

    // 3) S(fp16 smem) + softmax -> attn fp32 + P fp16 (g_ah), 2 CTAs/SM
    sscore_kernel<<<BH_ * 32, 256, SS_SMEM>>>(attn);

    // 4) ctx = P(fp16) @ Vh
    av_gemm<<<dim3(1, N_ / 128, BH_), 256, AV_SMEM>>>();

    // 5) out = ctx @ w_proj + bias
    proj_gemm<<<dim3(C_ / 128, M_ / 128), 256, PJ_SMEM>>>(out, b_proj);
}

// round 17
// speedup vs baseline: 1.1935x; 1.0225x over previous
#include <cuda_runtime.h>
#include <cuda_fp16.h>

typedef unsigned int u32;

#define B_   8
#define N_   1024
#define C_   1024
#define H_   16
#define D_   64
#define M_   (B_ * N_)     // 8192
#define QKVC 3072
#define BH_  (B_ * H_)     // 128

// ---------------- allocation-free scratch (device globals, fp16) ----------
__device__ __align__(256) __half g_xh[(size_t)M_ * C_];
__device__ __align__(256) __half g_wqh[(size_t)QKVC * C_];
__device__ __align__(256) __half g_wph[(size_t)C_ * C_];
__device__ __align__(256) __half g_qh[(size_t)BH_ * N_ * D_];
__device__ __align__(256) __half g_kh[(size_t)BH_ * N_ * D_];
__device__ __align__(256) __half g_vTh[(size_t)BH_ * D_ * N_];
__device__ __align__(256) __half g_ch[(size_t)M_ * C_];
__device__ __align__(256) __half g_ah[(size_t)BH_ * N_ * N_];   // fp16 P handoff

// ---------------- helpers ----------------
__device__ __forceinline__ u32 smem_u32(const void* p) {
    u32 a;
    asm("{ .reg .u64 t; cvta.to.shared.u64 t, %1; cvt.u32.u64 %0, t; }" : "=r"(a) : "l"(p));
    return a;
}
#define CP16(dst, src) \
    asm volatile("cp.async.cg.shared.global [%0], [%1], 16;" :: "r"(dst), "l"(src) : "memory")
#define CP_COMMIT() asm volatile("cp.async.commit_group;" ::: "memory")
#define CP_WAIT(n)  asm volatile("cp.async.wait_group %0;" :: "n"(n) : "memory")

__device__ __forceinline__ void ldm4(u32& r0, u32& r1, u32& r2, u32& r3, u32 a) {
    asm volatile("ldmatrix.sync.aligned.m8n8.x4.shared.b16 {%0,%1,%2,%3}, [%4];"
        : "=r"(r0), "=r"(r1), "=r"(r2), "=r"(r3) : "r"(a));
}
__device__ __forceinline__ void mma16816(float* c, const u32* a, const u32* b) {
    asm volatile(
        "mma.sync.aligned.m16n8k16.row.col.f32.f16.f16.f32 "
        "{%0,%1,%2,%3}, {%4,%5,%6,%7}, {%8,%9}, {%0,%1,%2,%3};"
        : "+f"(c[0]), "+f"(c[1]), "+f"(c[2]), "+f"(c[3])
        : "r"(a[0]), "r"(a[1]), "r"(a[2]), "r"(a[3]), "r"(b[0]), "r"(b[1]));
}

// ---------------------------------------------------------------------------
// QKV GEMM: 1-term fp16. 256 thr, 2 CTAs/SM, MA4 NA4, 3-stage ring. (r13)
// ---------------------------------------------------------------------------
#define QK_PART  10240
#define QK_STAGE (2 * QK_PART)
#define QK_SMEM  (3 * QK_STAGE)   // 61440

__global__ void __launch_bounds__(256, 2) qkv_gemm()
{
    constexpr int NC = 32;
    constexpr int MA = 4;
    constexpr int NA = 4;

    extern __shared__ char smem[];
    const u32 sb   = smem_u32(smem);
    const int tid  = threadIdx.x;
    const int wid  = tid >> 5, lane = tid & 31;
    const int g    = lane >> 2, t = lane & 3;
    const int bn   = blockIdx.x * 128;
    const int bm   = blockIdx.y * 128;
    const int wm   = (wid & 1) * 64;
    const int wn   = (wid >> 1) * 32;

    const __half *Ah = g_xh + (size_t)bm * C_;
    const __half *Bh = g_wqh + (size_t)bn * C_;

    float acc[MA][NA][4];
    #pragma unroll
    for (int i = 0; i < MA; i++)
        #pragma unroll
        for (int j = 0; j < NA; j++)
            #pragma unroll
            for (int r = 0; r < 4; r++) acc[i][j][r] = 0.0f;

    auto issue_loads = [&](int ck, int s) {
        const int kofs = ck * 32;
        const u32 base = sb + s * QK_STAGE;
        #pragma unroll
        for (int i = tid; i < 128 * 4; i += 256) {
            int r = i >> 2, sgm = i & 3;
            u32 off = (u32)(r * 80 + sgm * 16);
            const size_t go = (size_t)r * C_ + kofs + sgm * 8;
            CP16(base + off,           Ah + go);
            CP16(base + QK_PART + off, Bh + go);
        }
        CP_COMMIT();
    };

    const u32 arow = (u32)((wm + (lane & 15)) * 80 + ((lane >> 4) << 4));
    const u32 brow = (u32)((wn + (lane & 7) + ((lane >> 4) << 3)) * 80 + (((lane >> 3) & 1) << 4));

    auto do_compute = [&](int s) {
        const u32 abase = sb + s * QK_STAGE;
        const u32 bbase = abase + QK_PART;
        #pragma unroll
        for (int ks = 0; ks < 2; ks++) {
            const u32 kb = ks * 32;
            u32 a_hi[MA][4], b_hi[NA][2];
            #pragma unroll
            for (int ma = 0; ma < MA; ma++) {
                u32 ad = abase + arow + ma * 16 * 80 + kb;
                ldm4(a_hi[ma][0], a_hi[ma][1], a_hi[ma][2], a_hi[ma][3], ad);
            }
            #pragma unroll
            for (int p = 0; p < NA / 2; p++) {
                u32 bd = bbase + brow + p * 16 * 80 + kb;
                ldm4(b_hi[2*p][0], b_hi[2*p][1], b_hi[2*p+1][0], b_hi[2*p+1][1], bd);
            }
            #pragma unroll
            for (int ma = 0; ma < MA; ma++)
                #pragma unroll
                for (int na = 0; na < NA; na++)
                    mma16816(acc[ma][na], a_hi[ma], b_hi[na]);
        }
    };

    issue_loads(0, 0);
    issue_loads(1, 1);
    for (int ck = 0; ck < NC; ck++) {
        const int s = ck % 3;
        if (ck + 2 < NC) { issue_loads(ck + 2, (ck + 2) % 3); CP_WAIT(2); }
        else if (ck + 1 < NC) { CP_WAIT(1); }
        else { CP_WAIT(0); }
        __syncthreads();
        do_compute(s);
        __syncthreads();
    }

    #pragma unroll
    for (int ma = 0; ma < MA; ma++)
        #pragma unroll
        for (int na = 0; na < NA; na++)
            #pragma unroll
            for (int half = 0; half < 2; half++) {
                const int row = bm + wm + ma * 16 + g + half * 8;
                const int col = bn + wn + na * 8 + t * 2;
                float v0 = acc[ma][na][half * 2 + 0];
                float v1 = acc[ma][na][half * 2 + 1];

                const int which = col >> 10;
                const int c     = col & 1023;
                const int h     = c >> 6;
                const int d0    = c & 63;
                const int b8    = row >> 10;
                const int n     = row & 1023;
                const int bh    = b8 * H_ + h;
                if (which == 0) {
                    const size_t base = ((size_t)bh * N_ + n) * D_ + d0;
                    *(__half2*)(g_qh + base) =
                        __halves2half2(__float2half(v0 * 0.125f), __float2half(v1 * 0.125f));
                } else if (which == 1) {
                    const size_t base = ((size_t)bh * N_ + n) * D_ + d0;
                    *(__half2*)(g_kh + base) =
                        __halves2half2(__float2half(v0), __float2half(v1));
                } else {
                    const size_t vb = (size_t)bh * D_ * N_ + n;
                    g_vTh[vb + (size_t)d0 * N_]       = __float2half(v0);
                    g_vTh[vb + (size_t)(d0 + 1) * N_] = __float2half(v1);
                }
            }
}

// ---------------------------------------------------------------------------
// S = qh @ kh^T (fp16 scores in smem) -> softmax -> attn fp32 + P fp16. (r16)
// ---------------------------------------------------------------------------
#define Q_OFF   0
#define K_OFF   4608
#define KSTG    18432
#define S_OFF   41472
#define S_PIT2  2080
#define SS_SMEM (S_OFF + 32 * S_PIT2)   // 108032

__global__ void __launch_bounds__(256, 2) sscore_kernel(float* __restrict__ attn)
{
    extern __shared__ char smem[];
    const u32 sb   = smem_u32(smem);
    const int tid  = threadIdx.x;
    const int wid  = tid >> 5, lane = tid & 31;
    const int g    = lane >> 2, t = lane & 3;

    const int bh   = blockIdx.x >> 5;
    const int row0 = (blockIdx.x & 31) * 32;
    const int wm   = (wid & 1) * 16;
    const int wn   = (wid >> 1) * 32;

    const __half* Qh = g_qh + ((size_t)bh * N_ + row0) * D_;
    const __half* Kh = g_kh + (size_t)bh * N_ * D_;

    {
        int r = tid >> 3, sgm = tid & 7;
        u32 off = (u32)(r * 144 + sgm * 16);
        *(float4*)(smem + Q_OFF + off) = *(const float4*)(Qh + r * D_ + sgm * 8);
    }

    auto issueK = [&](int c, int s) {
        const u32 base = sb + K_OFF + s * KSTG;
        const size_t ko = (size_t)c * 128 * D_;
        #pragma unroll
        for (int i = tid; i < 128 * 8; i += 256) {
            int r = i >> 3, sgm = i & 7;
            CP16(base + (u32)(r * 144 + sgm * 16), Kh + ko + r * D_ + sgm * 8);
        }
        CP_COMMIT();
    };

    const u32 arow = (u32)((wm + (lane & 15)) * 144 + ((lane >> 4) << 4));
    const u32 brow = (u32)((wn + (lane & 7) + ((lane >> 4) << 3)) * 144 + (((lane >> 3) & 1) << 4));

    issueK(0, 0);
    issueK(1, 1);
    for (int c = 0; c < 8; c++) {
        if (c < 7) CP_WAIT(1); else CP_WAIT(0);
        __syncthreads();

        const u32 kb0 = sb + K_OFF + (c & 1) * KSTG;
        float acc[4][4];
        #pragma unroll
        for (int j = 0; j < 4; j++)
            #pragma unroll
            for (int r = 0; r < 4; r++) acc[j][r] = 0.0f;

        #pragma unroll
        for (int ks = 0; ks < 4; ks++) {
            const u32 kb = ks * 32;
            u32 a_hi[4], b_hi[4][2];
            ldm4(a_hi[0], a_hi[1], a_hi[2], a_hi[3], sb + Q_OFF + arow + kb);
            #pragma unroll
            for (int p = 0; p < 2; p++) {
                u32 bd = kb0 + brow + p * 16 * 144 + kb;
                ldm4(b_hi[2*p][0], b_hi[2*p][1], b_hi[2*p+1][0], b_hi[2*p+1][1], bd);
            }
            #pragma unroll
            for (int na = 0; na < 4; na++)
                mma16816(acc[na], a_hi, b_hi[na]);
        }

        #pragma unroll
        for (int na = 0; na < 4; na++)
            #pragma unroll
            for (int half = 0; half < 2; half++) {
                int row = wm + g + half * 8;
                int col = c * 128 + wn + na * 8 + t * 2;
                *(__half2*)(smem + S_OFF + row * S_PIT2 + col * 2) =
                    __halves2half2(__float2half(acc[na][half * 2]),
                                   __float2half(acc[na][half * 2 + 1]));
            }

        __syncthreads();
        if (c + 2 < 8) issueK(c + 2, c & 1);
    }

    #pragma unroll
    for (int rr = 0; rr < 4; rr++) {
        const int r = wid * 4 + rr;
        const char* Srow = smem + S_OFF + r * S_PIT2;
        float f[4][8];
        float m = -1e30f;
        #pragma unroll
        for (int i = 0; i < 4; i++) {
            uint4 raw = *(const uint4*)(Srow + lane * 16 + i * 512);
            const u32 w[4] = { raw.x, raw.y, raw.z, raw.w };
            #pragma unroll
            for (int j = 0; j < 4; j++) {
                float2 v = __half22float2(*(const __half2*)&w[j]);
                f[i][2*j]   = v.x;
                f[i][2*j+1] = v.y;
                m = fmaxf(m, fmaxf(v.x, v.y));
            }
        }
        #pragma unroll
        for (int o = 16; o > 0; o >>= 1) m = fmaxf(m, __shfl_xor_sync(0xffffffffu, m, o));
        float s = 0.0f;
        #pragma unroll
        for (int i = 0; i < 4; i++)
            #pragma unroll
            for (int j = 0; j < 8; j++) {
                f[i][j] = __expf(f[i][j] - m);
                s += f[i][j];
            }
        #pragma unroll
        for (int o = 16; o > 0; o >>= 1) s += __shfl_xor_sync(0xffffffffu, s, o);
        const float inv = 1.0f / s;

        const size_t gr = (size_t)bh * N_ + row0 + r;
        float* ap = attn + gr * N_;
        __half* php = g_ah + gr * N_;
        #pragma unroll
        for (int i = 0; i < 4; i++) {
            const int c0 = lane * 8 + i * 256;
            float p[8];
            #pragma unroll
            for (int j = 0; j < 8; j++) p[j] = f[i][j] * inv;
            *(float4*)(ap + c0)     = make_float4(p[0], p[1], p[2], p[3]);
            *(float4*)(ap + c0 + 4) = make_float4(p[4], p[5], p[6], p[7]);
            __half2 h0 = __halves2half2(__float2half(p[0]), __float2half(p[1]));
            __half2 h1 = __halves2half2(__float2half(p[2]), __float2half(p[3]));
            __half2 h2 = __halves2half2(__float2half(p[4]), __float2half(p[5]));
            __half2 h3 = __halves2half2(__float2half(p[6]), __float2half(p[7]));
            *(uint4*)(php + c0) = make_uint4(*(u32*)&h0, *(u32*)&h1, *(u32*)&h2, *(u32*)&h3);
        }
    }
}

// ---------------------------------------------------------------------------
// AV GEMM: ctx = Ph @ Vh. K-chunk 64, 3-stage, 2 CTAs/SM.
// Smem: A 128x144 (18432) + V 64x144 (9216) per stage; 3 x 27648 = 82944.
// ---------------------------------------------------------------------------
#define AV_APART 18432
#define AV_STAGE 27648
#define AV_SMEM  (3 * AV_STAGE)   // 82944

__global__ void __launch_bounds__(256, 2) av_gemm()
{
    constexpr int NC = 16;
    extern __shared__ char smem[];
    const u32 sb   = smem_u32(smem);
    const int tid  = threadIdx.x;
    const int wid  = tid >> 5, lane = tid & 31;
    const int g    = lane >> 2, t = lane & 3;

    const int bm = blockIdx.y * 128;
    const int z  = blockIdx.z;
    const int b8 = z >> 4, h = z & 15;
    const int wm = (wid & 3) * 32;
    const int wn = (wid >> 2) * 32;

    const __half* Ap = g_ah + (size_t)z * N_ * N_ + (size_t)bm * N_;
    const __half* Vh = g_vTh + (size_t)z * D_ * N_;

    float acc[2][4][4];
    #pragma unroll
    for (int i = 0; i < 2; i++)
        #pragma unroll
        for (int j = 0; j < 4; j++)
            #pragma unroll
            for (int r = 0; r < 4; r++) acc[i][j][r] = 0.0f;

    auto issue_loads = [&](int ck, int s) {
        const int kofs = ck * 64;
        const u32 abase = sb + s * AV_STAGE;
        #pragma unroll
        for (int i = tid; i < 128 * 8; i += 256) {
            int r = i >> 3, sgm = i & 7;
            CP16(abase + (u32)(r * 144 + sgm * 16), Ap + (size_t)r * N_ + kofs + sgm * 8);
        }
        const u32 bbase = abase + AV_APART;
        #pragma unroll
        for (int i = tid; i < 64 * 8; i += 256) {
            int r = i >> 3, sgm = i & 7;
            CP16(bbase + (u32)(r * 144 + sgm * 16), Vh + (size_t)r * N_ + kofs + sgm * 8);
        }
        CP_COMMIT();
    };

    const u32 arow = (u32)((wm + (lane & 15)) * 144 + ((lane >> 4) << 4));
    const u32 brow = (u32)((wn + (lane & 7) + ((lane >> 4) << 3)) * 144 + (((lane >> 3) & 1) << 4));

    issue_loads(0, 0);
    issue_loads(1, 1);
    for (int ck = 0; ck < NC; ck++) {
        const int s = ck % 3;
        if (ck + 2 < NC) { issue_loads(ck + 2, (ck + 2) % 3); CP_WAIT(2); }
        else if (ck + 1 < NC) { CP_WAIT(1); }
        else { CP_WAIT(0); }
        __syncthreads();

        const u32 ah0 = sb + s * AV_STAGE;
        const u32 bb0 = ah0 + AV_APART;
        #pragma unroll
        for (int ks = 0; ks < 4; ks++) {
            const u32 kb = ks * 32;
            u32 a_hi[2][4], b_hi[4][2];
            #pragma unroll
            for (int ma = 0; ma < 2; ma++) {
                u32 ad = ah0 + arow + ma * 16 * 144 + kb;
                ldm4(a_hi[ma][0], a_hi[ma][1], a_hi[ma][2], a_hi[ma][3], ad);
            }
            #pragma unroll
            for (int p = 0; p < 2; p++) {
                u32 bd = bb0 + brow + p * 16 * 144 + kb;
                ldm4(b_hi[2*p][0], b_hi[2*p][1], b_hi[2*p+1][0], b_hi[2*p+1][1], bd);
            }
            #pragma unroll
            for (int ma = 0; ma < 2; ma++)
                #pragma unroll
                for (int na = 0; na < 4; na++)
                    mma16816(acc[ma][na], a_hi[ma], b_hi[na]);
        }
        __syncthreads();
    }

    #pragma unroll
    for (int ma = 0; ma < 2; ma++)
        #pragma unroll
        for (int na = 0; na < 4; na++)
            #pragma unroll
            for (int half = 0; half < 2; half++) {
                const int row = bm + wm + ma * 16 + g + half * 8;
                const int col = wn + na * 8 + t * 2;
                const size_t base = ((size_t)(b8 * N_ + row)) * C_ + h * 64 + col;
                *(__half2*)(g_ch + base) =
                    __halves2half2(__float2half(acc[ma][na][half * 2 + 0]),
                                   __float2half(acc[ma][na][half * 2 + 1]));
            }
}

// ---------------------------------------------------------------------------
// Projection GEMM: out = ch @ wph + bias. K-chunk 64, 3-stage, 2 CTAs/SM.
// Smem: A 128x144 + B 128x144 per stage; 3 x 36864 = 110592.
// ---------------------------------------------------------------------------
#define PJ_PART  18432
#define PJ_STAGE 36864
#define PJ_SMEM  (3 * PJ_STAGE)   // 110592

__global__ void __launch_bounds__(256, 2) proj_gemm(float* __restrict__ out,
                                                    const float* __restrict__ bias)
{
    constexpr int NC = 16;
    constexpr int MA = 4;
    constexpr int NA = 4;

    extern __shared__ char smem[];
    const u32 sb   = smem_u32(smem);
    const int tid  = threadIdx.x;
    const int wid  = tid >> 5, lane = tid & 31;
    const int g    = lane >> 2, t = lane & 3;
    const int bn   = blockIdx.x * 128;
    const int bm   = blockIdx.y * 128;
    const int wm   = (wid & 1) * 64;
    const int wn   = (wid >> 1) * 32;

    const __half *Ah = g_ch + (size_t)bm * C_;
    const __half *Bh = g_wph + (size_t)bn * C_;

    float acc[MA][NA][4];
    #pragma unroll
    for (int i = 0; i < MA; i++)
        #pragma unroll
        for (int j = 0; j < NA; j++)
            #pragma unroll
            for (int r = 0; r < 4; r++) acc[i][j][r] = 0.0f;

    auto issue_loads = [&](int ck, int s) {
        const int kofs = ck * 64;
        const u32 base = sb + s * PJ_STAGE;
        #pragma unroll
        for (int i = tid; i < 128 * 8; i += 256) {
            int r = i >> 3, sgm = i & 7;
            u32 off = (u32)(r * 144 + sgm * 16);
            const size_t go = (size_t)r * C_ + kofs + sgm * 8;
            CP16(base + off,           Ah + go);
            CP16(base + PJ_PART + off, Bh + go);
        }
        CP_COMMIT();
    };

    const u32 arow = (u32)((wm + (lane & 15)) * 144 + ((lane >> 4) << 4));
    const u32 brow = (u32)((wn + (lane & 7) + ((lane >> 4) << 3)) * 144 + (((lane >> 3) & 1) << 4));

    auto do_compute = [&](int s) {
        const u32 abase = sb + s * PJ_STAGE;
        const u32 bbase = abase + PJ_PART;
        #pragma unroll
        for (int ks = 0; ks < 4; ks++) {
            const u32 kb = ks * 32;
            u32 a_hi[MA][4], b_hi[NA][2];
            #pragma unroll
            for (int ma = 0; ma < MA; ma++) {
                u32 ad = abase + arow + ma * 16 * 144 + kb;
                ldm4(a_hi[ma][0], a_hi[ma][1], a_hi[ma][2], a_hi[ma][3], ad);
            }
            #pragma unroll
            for (int p = 0; p < NA / 2; p++) {
                u32 bd = bbase + brow + p * 16 * 144 + kb;
                ldm4(b_hi[2*p][0], b_hi[2*p][1], b_hi[2*p+1][0], b_hi[2*p+1][1], bd);
            }
            #pragma unroll
            for (int ma = 0; ma < MA; ma++)
                #pragma unroll
                for (int na = 0; na < NA; na++)
                    mma16816(acc[ma][na], a_hi[ma], b_hi[na]);
        }
    };

    issue_loads(0, 0);
    issue_loads(1, 1);
    for (int ck = 0; ck < NC; ck++) {
        const int s = ck % 3;
        if (ck + 2 < NC) { issue_loads(ck + 2, (ck + 2) % 3); CP_WAIT(2); }
        else if (ck + 1 < NC) { CP_WAIT(1); }
        else { CP_WAIT(0); }
        __syncthreads();
        do_compute(s);
        __syncthreads();
    }

    #pragma unroll
    for (int ma = 0; ma < MA; ma++)
        #pragma unroll
        for (int na = 0; na < NA; na++)
            #pragma unroll
            for (int half = 0; half < 2; half++) {
                const int row = bm + wm + ma * 16 + g + half * 8;
                const int col = bn + wn + na * 8 + t * 2;
                float* dst = out + (size_t)row * C_ + col;
                *(float2*)dst = make_float2(acc[ma][na][half * 2 + 0] + bias[col],
                                            acc[ma][na][half * 2 + 1] + bias[col + 1]);
            }
}

// ---------------- conversion kernels ----------------
__global__ void __launch_bounds__(256) conv_x(const float* __restrict__ s)
{
    int i = blockIdx.x * 256 + threadIdx.x;
    float4 v = ((const float4*)s)[i];
    __half2* hp = (__half2*)g_xh;
    hp[i * 2]     = __halves2half2(__float2half(v.x), __float2half(v.y));
    hp[i * 2 + 1] = __halves2half2(__float2half(v.z), __float2half(v.w));
}

template <int W>
__global__ void __launch_bounds__(256) conv_wT(const float* __restrict__ s)
{
    constexpr int Cc = (W == 0) ? QKVC : C_;
    __half* dh = (W == 0) ? g_wqh : g_wph;

    __shared__ float tbuf[32][33];
    const int tx = threadIdx.x & 31, ty = threadIdx.x >> 5;
    const int c0 = blockIdx.x * 32, r0 = blockIdx.y * 32;
    #pragma unroll
    for (int j = 0; j < 4; j++)
        tbuf[ty + j * 8][tx] = s[(size_t)(r0 + ty + j * 8) * Cc + c0 + tx];
    __syncthreads();
    #pragma unroll
    for (int j = 0; j < 4; j++) {
        int i = ty + j * 8;
        dh[(size_t)(c0 + i) * C_ + r0 + tx] = __float2half(tbuf[tx][i]);
    }
}

// ---------------------------------------------------------------------------
extern "C" void kernel_launch(void* const* d_in, const int* in_sizes, int n_in,
                              void* d_out, int out_size)
{
    const float* x      = (const float*)d_in[0];
    const float* w_qkv  = (const float*)d_in[1];
    const float* w_proj = (const float*)d_in[2];
    const float* b_proj = (const float*)d_in[3];
    float* out  = (float*)d_out;
    float* attn = out + (size_t)M_ * C_;

    cudaFuncSetAttribute(qkv_gemm,      cudaFuncAttributeMaxDynamicSharedMemorySize, QK_SMEM);
    cudaFuncSetAttribute(sscore_kernel, cudaFuncAttributeMaxDynamicSharedMemorySize, SS_SMEM);
    cudaFuncSetAttribute(av_gemm,       cudaFuncAttributeMaxDynamicSharedMemorySize, AV_SMEM);
    cudaFuncSetAttribute(proj_gemm,     cudaFuncAttributeMaxDynamicSharedMemorySize, PJ_SMEM);

    // 1) input conversions (plain fp16)
    conv_x<<<M_ * C_ / 1024, 256>>>(x);
    conv_wT<0><<<dim3(QKVC / 32, C_ / 32), 256>>>(w_qkv);
    conv_wT<1><<<dim3(C_ / 32, C_ / 32), 256>>>(w_proj);

    // 2) QKV GEMM (1-term) -> q (scaled), k, vT
    qkv_gemm<<<dim3(QKVC / 128, M_ / 128), 256, QK_SMEM>>>();

    // 3) S(fp16 smem) + softmax -> attn fp32 + P fp16 (g_ah)
    sscore_kernel<<<BH_ * 32, 256, SS_SMEM>>>(attn);

    // 4) ctx = P(fp16) @ Vh (K-chunk 64)
    av_gemm<<<dim3(1, N_ / 128, BH_), 256, AV_SMEM>>>();

    // 5) out = ctx @ w_proj + bias (K-chunk 64)
    proj_gemm<<<dim3(C_ / 128, M_ / 128), 256, PJ_SMEM>>>(out, b_proj);
}